// round 1
// baseline (speedup 1.0000x reference)
#include <cuda_runtime.h>

// Person2Relation: out[b,p,:] = relu([f_i|f_j] W1^T + b1) W2^T + b2
// Restructured: A[b,n,:] = f_n @ W1[:, :512]^T ; Bm[b,n,:] = f_n @ W1[:, 512:]^T
//               h[b,(i,j),:] = relu(A[b,i,:] + Bm[b,j,:] + b1)
//               out = h @ W2^T + b2
static constexpr int BATCH = 64;
static constexpr int NPER  = 32;
static constexpr int D     = 512;
static constexpr int NP    = 992;   // 32*31 ordered pairs

// scratch: [2048][1024]  (cols 0..511 = A part, 512..1023 = B part)
__device__ float g_AB[BATCH * NPER * 2 * D];

// ---------------------------------------------------------------------------
// Kernel 1: C[m, o] = sum_k F[m,k] * Wc[k,o],  M=2048, N=1024, K=512
//   Wc[k,o] = (o<512) ? W1[o, k] : W1[o-512, 512+k]
// 128x128x8 SGEMM, 256 threads, 8x8 microtile, double-buffered smem.
// ---------------------------------------------------------------------------
__global__ void __launch_bounds__(256)
k1_proj(const float* __restrict__ pf, const float* __restrict__ W1)
{
    __shared__ float As[2][8][128];
    __shared__ float Bs[2][8][128];

    const int t  = threadIdx.x;
    const int m0 = blockIdx.x * 128;
    const int o0 = blockIdx.y * 128;
    const int tx = t & 15;          // 16 cols of 8
    const int ty = t >> 4;          // 16 rows of 8

    const int base = t * 4;
    const int lm = base >> 3;       // 0..127
    const int lk = base & 7;        // 0 or 4

    const int o = o0 + lm;
    const float* wbase = (o < D) ? (W1 + (size_t)o * (2 * D) + lk)
                                 : (W1 + (size_t)(o - D) * (2 * D) + D + lk);
    const float* abase = pf + (size_t)(m0 + lm) * D + lk;

    float acc[8][8];
#pragma unroll
    for (int i = 0; i < 8; i++)
#pragma unroll
        for (int j = 0; j < 8; j++) acc[i][j] = 0.f;

    float4 ra = *(const float4*)(abase);
    float4 rb = *(const float4*)(wbase);

    As[0][lk + 0][lm] = ra.x; As[0][lk + 1][lm] = ra.y;
    As[0][lk + 2][lm] = ra.z; As[0][lk + 3][lm] = ra.w;
    Bs[0][lk + 0][lm] = rb.x; Bs[0][lk + 1][lm] = rb.y;
    Bs[0][lk + 2][lm] = rb.z; Bs[0][lk + 3][lm] = rb.w;
    __syncthreads();

    const int NT = D / 8;   // 64
    int buf = 0;
    for (int kt = 0; kt < NT; kt++) {
        if (kt + 1 < NT) {
            ra = *(const float4*)(abase + (kt + 1) * 8);
            rb = *(const float4*)(wbase + (kt + 1) * 8);
        }
#pragma unroll
        for (int k = 0; k < 8; k++) {
            float4 a0 = *(const float4*)&As[buf][k][ty * 8];
            float4 a1 = *(const float4*)&As[buf][k][ty * 8 + 4];
            float4 b0 = *(const float4*)&Bs[buf][k][tx * 8];
            float4 b1v= *(const float4*)&Bs[buf][k][tx * 8 + 4];
            float av[8] = {a0.x,a0.y,a0.z,a0.w,a1.x,a1.y,a1.z,a1.w};
            float bv[8] = {b0.x,b0.y,b0.z,b0.w,b1v.x,b1v.y,b1v.z,b1v.w};
#pragma unroll
            for (int i = 0; i < 8; i++)
#pragma unroll
                for (int j = 0; j < 8; j++)
                    acc[i][j] = fmaf(av[i], bv[j], acc[i][j]);
        }
        if (kt + 1 < NT) {
            const int nb = buf ^ 1;
            As[nb][lk + 0][lm] = ra.x; As[nb][lk + 1][lm] = ra.y;
            As[nb][lk + 2][lm] = ra.z; As[nb][lk + 3][lm] = ra.w;
            Bs[nb][lk + 0][lm] = rb.x; Bs[nb][lk + 1][lm] = rb.y;
            Bs[nb][lk + 2][lm] = rb.z; Bs[nb][lk + 3][lm] = rb.w;
        }
        __syncthreads();
        buf ^= 1;
    }

#pragma unroll
    for (int i = 0; i < 8; i++) {
        const int m = m0 + ty * 8 + i;
        float* cp = g_AB + (size_t)m * (2 * D) + o0 + tx * 8;
        float4 v0 = {acc[i][0], acc[i][1], acc[i][2], acc[i][3]};
        float4 v1 = {acc[i][4], acc[i][5], acc[i][6], acc[i][7]};
        *(float4*)(cp)     = v0;
        *(float4*)(cp + 4) = v1;
    }
}

// ---------------------------------------------------------------------------
// Kernel 2: out[b, p, d] = sum_k relu(A[b,i(p),k] + Bm[b,j(p),k] + b1[k]) * W2[d,k] + b2[d]
// A-operand tile generated on the fly; B-operand = W2 rows (contiguous in k).
// ---------------------------------------------------------------------------
__global__ void __launch_bounds__(256)
k2_pair(const float* __restrict__ W2, const float* __restrict__ b1,
        const float* __restrict__ b2, float* __restrict__ out)
{
    __shared__ float As[2][8][128];
    __shared__ float Bs[2][8][128];

    const int t  = threadIdx.x;
    const int bb = blockIdx.z;
    const int m0 = blockIdx.x * 128;   // pair tile
    const int n0 = blockIdx.y * 128;   // output-d tile
    const int tx = t & 15;
    const int ty = t >> 4;

    const int base = t * 4;
    const int lm = base >> 3;
    const int lk = base & 7;

    const int p = m0 + lm;
    const bool pv = (p < NP);
    int i = 0, j = 0;
    if (pv) { i = p / 31; const int r = p - i * 31; j = r + (r >= i ? 1 : 0); }

    const float* aI = g_AB + (size_t)(bb * NPER + i) * (2 * D) + lk;          // A part
    const float* aJ = g_AB + (size_t)(bb * NPER + j) * (2 * D) + D + lk;      // B part
    const float* wb = W2 + (size_t)(n0 + lm) * D + lk;

    float acc[8][8];
#pragma unroll
    for (int ii = 0; ii < 8; ii++)
#pragma unroll
        for (int jj = 0; jj < 8; jj++) acc[ii][jj] = 0.f;

    float4 rh, rb;
    {
        float4 xa = *(const float4*)(aI);
        float4 xb = *(const float4*)(aJ);
        float4 bs = *(const float4*)(b1 + lk);
        rh.x = pv ? fmaxf(xa.x + xb.x + bs.x, 0.f) : 0.f;
        rh.y = pv ? fmaxf(xa.y + xb.y + bs.y, 0.f) : 0.f;
        rh.z = pv ? fmaxf(xa.z + xb.z + bs.z, 0.f) : 0.f;
        rh.w = pv ? fmaxf(xa.w + xb.w + bs.w, 0.f) : 0.f;
        rb = *(const float4*)(wb);
    }
    As[0][lk + 0][lm] = rh.x; As[0][lk + 1][lm] = rh.y;
    As[0][lk + 2][lm] = rh.z; As[0][lk + 3][lm] = rh.w;
    Bs[0][lk + 0][lm] = rb.x; Bs[0][lk + 1][lm] = rb.y;
    Bs[0][lk + 2][lm] = rb.z; Bs[0][lk + 3][lm] = rb.w;
    __syncthreads();

    const int NT = D / 8;   // 64
    int buf = 0;
    for (int kt = 0; kt < NT; kt++) {
        if (kt + 1 < NT) {
            float4 xa = *(const float4*)(aI + (kt + 1) * 8);
            float4 xb = *(const float4*)(aJ + (kt + 1) * 8);
            float4 bs = *(const float4*)(b1 + (kt + 1) * 8 + lk);
            rh.x = pv ? fmaxf(xa.x + xb.x + bs.x, 0.f) : 0.f;
            rh.y = pv ? fmaxf(xa.y + xb.y + bs.y, 0.f) : 0.f;
            rh.z = pv ? fmaxf(xa.z + xb.z + bs.z, 0.f) : 0.f;
            rh.w = pv ? fmaxf(xa.w + xb.w + bs.w, 0.f) : 0.f;
            rb = *(const float4*)(wb + (kt + 1) * 8);
        }
#pragma unroll
        for (int k = 0; k < 8; k++) {
            float4 a0 = *(const float4*)&As[buf][k][ty * 8];
            float4 a1 = *(const float4*)&As[buf][k][ty * 8 + 4];
            float4 b0 = *(const float4*)&Bs[buf][k][tx * 8];
            float4 b1v= *(const float4*)&Bs[buf][k][tx * 8 + 4];
            float av[8] = {a0.x,a0.y,a0.z,a0.w,a1.x,a1.y,a1.z,a1.w};
            float bv[8] = {b0.x,b0.y,b0.z,b0.w,b1v.x,b1v.y,b1v.z,b1v.w};
#pragma unroll
            for (int ii = 0; ii < 8; ii++)
#pragma unroll
                for (int jj = 0; jj < 8; jj++)
                    acc[ii][jj] = fmaf(av[ii], bv[jj], acc[ii][jj]);
        }
        if (kt + 1 < NT) {
            const int nb = buf ^ 1;
            As[nb][lk + 0][lm] = rh.x; As[nb][lk + 1][lm] = rh.y;
            As[nb][lk + 2][lm] = rh.z; As[nb][lk + 3][lm] = rh.w;
            Bs[nb][lk + 0][lm] = rb.x; Bs[nb][lk + 1][lm] = rb.y;
            Bs[nb][lk + 2][lm] = rb.z; Bs[nb][lk + 3][lm] = rb.w;
        }
        __syncthreads();
        buf ^= 1;
    }

    // epilogue: + b2, guarded store
    const int dcol = n0 + tx * 8;
    float4 bz0 = *(const float4*)(b2 + dcol);
    float4 bz1 = *(const float4*)(b2 + dcol + 4);
#pragma unroll
    for (int ii = 0; ii < 8; ii++) {
        const int pp = m0 + ty * 8 + ii;
        if (pp < NP) {
            float* op = out + ((size_t)(bb * NP + pp)) * D + dcol;
            float4 v0 = {acc[ii][0] + bz0.x, acc[ii][1] + bz0.y,
                         acc[ii][2] + bz0.z, acc[ii][3] + bz0.w};
            float4 v1 = {acc[ii][4] + bz1.x, acc[ii][5] + bz1.y,
                         acc[ii][6] + bz1.z, acc[ii][7] + bz1.w};
            *(float4*)(op)     = v0;
            *(float4*)(op + 4) = v1;
        }
    }
}

extern "C" void kernel_launch(void* const* d_in, const int* in_sizes, int n_in,
                              void* d_out, int out_size)
{
    const float* pf = (const float*)d_in[0];   // person_feats (64,32,512)
    const float* W1 = (const float*)d_in[1];   // (512, 1024)
    const float* b1 = (const float*)d_in[2];   // (512,)
    const float* W2 = (const float*)d_in[3];   // (512, 512)
    const float* b2 = (const float*)d_in[4];   // (512,)
    float* out = (float*)d_out;                // (64, 992, 512)

    dim3 g1(16, 8, 1);       // M=2048/128, N=1024/128
    k1_proj<<<g1, 256>>>(pf, W1);

    dim3 g2(8, 4, BATCH);    // ceil(992/128), 512/128, 64
    k2_pair<<<g2, 256>>>(W2, b1, b2, out);
}

// round 4
// speedup vs baseline: 1.8822x; 1.8822x over previous
#include <cuda_runtime.h>
#include <cuda_bf16.h>
#include <cstdint>

// Person2Relation: out[b,p,:] = relu([f_i|f_j] W1^T + b1) W2^T + b2
//   k1 (fp32 SGEMM): A[b,n,:]=f_n@W1[:,:512]^T ; Bm[b,n,:]=f_n@W1[:,512:]^T
//   k2 (bf16 HMMA, 3-term compensated): out = relu(A_i+Bm_j+b1) @ W2^T + b2
static constexpr int BATCH = 64;
static constexpr int NPER  = 32;
static constexpr int D     = 512;
static constexpr int NP    = 992;

__device__ float g_AB[BATCH * NPER * 2 * D];
__device__ __nv_bfloat16 g_W2hi[D * D];
__device__ __nv_bfloat16 g_W2lo[D * D];

__device__ __forceinline__ uint32_t smem_u32(const void* p) {
    uint32_t a;
    asm("{ .reg .u64 t; cvta.to.shared.u64 t, %1; cvt.u32.u64 %0, t; }" : "=r"(a) : "l"(p));
    return a;
}
__device__ __forceinline__ void ldm4(uint32_t* r, uint32_t addr) {
    asm volatile("ldmatrix.sync.aligned.m8n8.x4.shared.b16 {%0,%1,%2,%3}, [%4];"
                 : "=r"(r[0]), "=r"(r[1]), "=r"(r[2]), "=r"(r[3]) : "r"(addr));
}
__device__ __forceinline__ void mma16816(float* c, const uint32_t* a,
                                         uint32_t b0, uint32_t b1) {
    asm volatile(
        "mma.sync.aligned.m16n8k16.row.col.f32.bf16.bf16.f32 "
        "{%0,%1,%2,%3}, {%4,%5,%6,%7}, {%8,%9}, {%0,%1,%2,%3};"
        : "+f"(c[0]), "+f"(c[1]), "+f"(c[2]), "+f"(c[3])
        : "r"(a[0]), "r"(a[1]), "r"(a[2]), "r"(a[3]), "r"(b0), "r"(b1));
}
// pack two f32 -> bf16x2 (hi) and residual bf16x2 (lo)
__device__ __forceinline__ void pack2(float f0, float f1, uint32_t& hi, uint32_t& lo) {
    asm("cvt.rn.bf16x2.f32 %0, %1, %2;" : "=r"(hi) : "f"(f1), "f"(f0));
    float h0 = __uint_as_float(hi << 16);
    float h1 = __uint_as_float(hi & 0xFFFF0000u);
    float r0 = f0 - h0, r1 = f1 - h1;
    asm("cvt.rn.bf16x2.f32 %0, %1, %2;" : "=r"(lo) : "f"(r1), "f"(r0));
}

// ---------------------------------------------------------------------------
__global__ void k0_split(const float* __restrict__ W2) {
    int i = blockIdx.x * blockDim.x + threadIdx.x;
    if (i < D * D) {
        float w = W2[i];
        __nv_bfloat16 h = __float2bfloat16(w);
        g_W2hi[i] = h;
        g_W2lo[i] = __float2bfloat16(w - __bfloat162float(h));
    }
}

// ---------------------------------------------------------------------------
// k1: fp32 SGEMM  C[m,o] = sum_k F[m,k]*Wc[k,o], M=2048 N=1024 K=512
// ---------------------------------------------------------------------------
__global__ void __launch_bounds__(256)
k1_proj(const float* __restrict__ pf, const float* __restrict__ W1)
{
    __shared__ float As[2][8][128];
    __shared__ float Bs[2][8][128];

    const int t  = threadIdx.x;
    const int m0 = blockIdx.x * 128;
    const int o0 = blockIdx.y * 128;
    const int tx = t & 15;
    const int ty = t >> 4;
    const int base = t * 4;
    const int lm = base >> 3;
    const int lk = base & 7;

    const int o = o0 + lm;
    const float* wbase = (o < D) ? (W1 + (size_t)o * (2 * D) + lk)
                                 : (W1 + (size_t)(o - D) * (2 * D) + D + lk);
    const float* abase = pf + (size_t)(m0 + lm) * D + lk;

    float acc[8][8];
#pragma unroll
    for (int i = 0; i < 8; i++)
#pragma unroll
        for (int j = 0; j < 8; j++) acc[i][j] = 0.f;

    float4 ra = *(const float4*)(abase);
    float4 rb = *(const float4*)(wbase);
    As[0][lk+0][lm]=ra.x; As[0][lk+1][lm]=ra.y; As[0][lk+2][lm]=ra.z; As[0][lk+3][lm]=ra.w;
    Bs[0][lk+0][lm]=rb.x; Bs[0][lk+1][lm]=rb.y; Bs[0][lk+2][lm]=rb.z; Bs[0][lk+3][lm]=rb.w;
    __syncthreads();

    const int NT = D / 8;
    int buf = 0;
    for (int kt = 0; kt < NT; kt++) {
        if (kt + 1 < NT) {
            ra = *(const float4*)(abase + (kt + 1) * 8);
            rb = *(const float4*)(wbase + (kt + 1) * 8);
        }
#pragma unroll
        for (int k = 0; k < 8; k++) {
            float4 a0 = *(const float4*)&As[buf][k][ty*8];
            float4 a1 = *(const float4*)&As[buf][k][ty*8+4];
            float4 b0 = *(const float4*)&Bs[buf][k][tx*8];
            float4 b1v= *(const float4*)&Bs[buf][k][tx*8+4];
            float av[8] = {a0.x,a0.y,a0.z,a0.w,a1.x,a1.y,a1.z,a1.w};
            float bv[8] = {b0.x,b0.y,b0.z,b0.w,b1v.x,b1v.y,b1v.z,b1v.w};
#pragma unroll
            for (int i = 0; i < 8; i++)
#pragma unroll
                for (int j = 0; j < 8; j++)
                    acc[i][j] = fmaf(av[i], bv[j], acc[i][j]);
        }
        if (kt + 1 < NT) {
            const int nb = buf ^ 1;
            As[nb][lk+0][lm]=ra.x; As[nb][lk+1][lm]=ra.y; As[nb][lk+2][lm]=ra.z; As[nb][lk+3][lm]=ra.w;
            Bs[nb][lk+0][lm]=rb.x; Bs[nb][lk+1][lm]=rb.y; Bs[nb][lk+2][lm]=rb.z; Bs[nb][lk+3][lm]=rb.w;
        }
        __syncthreads();
        buf ^= 1;
    }
#pragma unroll
    for (int i = 0; i < 8; i++) {
        const int m = m0 + ty * 8 + i;
        float* cp = g_AB + (size_t)m * (2 * D) + o0 + tx * 8;
        float4 v0 = {acc[i][0], acc[i][1], acc[i][2], acc[i][3]};
        float4 v1 = {acc[i][4], acc[i][5], acc[i][6], acc[i][7]};
        *(float4*)(cp) = v0; *(float4*)(cp + 4) = v1;
    }
}

// ---------------------------------------------------------------------------
// k2: bf16 HMMA compensated GEMM. CTA 128x128, KC=32, 8 warps (2Mx4N), 64x32/warp.
// smem rows: 32 bf16 = 64B data, 80B stride (conflict-free ldmatrix).
// ---------------------------------------------------------------------------
static constexpr int KC     = 32;
static constexpr int CHUNKS = D / KC;     // 16
static constexpr int STR    = 80;         // bytes/row
static constexpr int TSZ    = 128 * STR;  // 10240 per tile array
static constexpr int OFF_B1 = 0;          // 2048B (b1)
static constexpr int BUF0   = 2048;
static constexpr int BUFSZ  = 4 * TSZ;    // AH, AL, BH, BL
static constexpr int SMEM_K2 = BUF0 + 2 * BUFSZ;   // 83968

struct Pref {
    float4 a[4], j[4];
    uint4  wh[2], wl[2];
};

__device__ __forceinline__ void loadPref(Pref& pr, const float* aI, const float* aJ,
                                         const __nv_bfloat16* whi,
                                         const __nv_bfloat16* wlo, int c) {
    const int k = c * KC;
#pragma unroll
    for (int q = 0; q < 4; q++) {
        pr.a[q] = *(const float4*)(aI + k + q * 4);
        pr.j[q] = *(const float4*)(aJ + k + q * 4);
    }
    pr.wh[0] = *(const uint4*)(whi + k);
    pr.wh[1] = *(const uint4*)(whi + k + 8);
    pr.wl[0] = *(const uint4*)(wlo + k);
    pr.wl[1] = *(const uint4*)(wlo + k + 8);
}

__device__ __forceinline__ void storePref(const Pref& pr, char* sm, int buf,
                                          int srow, bool pv, int c, int half) {
    const float* b1s = (const float*)(sm + OFF_B1) + c * KC + half * 16;
    uint32_t hi[8], lo[8];
#pragma unroll
    for (int q = 0; q < 4; q++) {
        float x0 = 0.f, x1 = 0.f, x2 = 0.f, x3 = 0.f;
        if (pv) {
            x0 = fmaxf(pr.a[q].x + pr.j[q].x + b1s[q*4+0], 0.f);
            x1 = fmaxf(pr.a[q].y + pr.j[q].y + b1s[q*4+1], 0.f);
            x2 = fmaxf(pr.a[q].z + pr.j[q].z + b1s[q*4+2], 0.f);
            x3 = fmaxf(pr.a[q].w + pr.j[q].w + b1s[q*4+3], 0.f);
        }
        pack2(x0, x1, hi[q*2+0], lo[q*2+0]);
        pack2(x2, x3, hi[q*2+1], lo[q*2+1]);
    }
    char* base = sm + BUF0 + buf * BUFSZ;
    *(uint4*)(base + 0*TSZ + srow +  0) = make_uint4(hi[0], hi[1], hi[2], hi[3]);
    *(uint4*)(base + 0*TSZ + srow + 16) = make_uint4(hi[4], hi[5], hi[6], hi[7]);
    *(uint4*)(base + 1*TSZ + srow +  0) = make_uint4(lo[0], lo[1], lo[2], lo[3]);
    *(uint4*)(base + 1*TSZ + srow + 16) = make_uint4(lo[4], lo[5], lo[6], lo[7]);
    *(uint4*)(base + 2*TSZ + srow +  0) = pr.wh[0];
    *(uint4*)(base + 2*TSZ + srow + 16) = pr.wh[1];
    *(uint4*)(base + 3*TSZ + srow +  0) = pr.wl[0];
    *(uint4*)(base + 3*TSZ + srow + 16) = pr.wl[1];
}

__global__ void __launch_bounds__(256, 1)
k2_mma(const float* __restrict__ b1g, const float* __restrict__ b2g,
       float* __restrict__ out)
{
    extern __shared__ char sm[];
    const uint32_t sb = smem_u32(sm);

    const int t = threadIdx.x, lane = t & 31, wid = t >> 5;
    const int b = blockIdx.z, m0 = blockIdx.x * 128, n0 = blockIdx.y * 128;

    if (t < 128) *(float4*)(sm + OFF_B1 + t * 16) = *(const float4*)(b1g + t * 4);
    __syncthreads();   // b1 staging must be visible before storePref reads it

    // producer mapping
    const int r = t >> 1, half = t & 1;
    const int srow = r * STR + half * 32;
    const int p = m0 + r;
    const bool pv = (p < NP);
    int pi = 0, pj = 0;
    if (pv) { pi = p / 31; int rr = p - pi * 31; pj = rr + (rr >= pi ? 1 : 0); }
    const float* aI = g_AB + (size_t)(b * NPER + pi) * (2 * D) + half * 16;
    const float* aJ = g_AB + (size_t)(b * NPER + pj) * (2 * D) + D + half * 16;
    const __nv_bfloat16* whi = g_W2hi + (size_t)(n0 + r) * D + half * 16;
    const __nv_bfloat16* wlo = g_W2lo + (size_t)(n0 + r) * D + half * 16;

    // mma mapping
    const int wm = (wid >> 2) * 64;
    const int wn = (wid & 3) * 32;
    const uint32_t lrow = (uint32_t)(lane & 15) * STR + (uint32_t)(lane >> 4) * 16;

    float c[4][4][4];
#pragma unroll
    for (int i = 0; i < 4; i++)
#pragma unroll
        for (int j = 0; j < 4; j++)
#pragma unroll
            for (int e = 0; e < 4; e++) c[i][j][e] = 0.f;

    Pref pr;
    loadPref(pr, aI, aJ, whi, wlo, 0);
    storePref(pr, sm, 0, srow, pv, 0, half);
    __syncthreads();

    for (int ch = 0; ch < CHUNKS; ch++) {
        const int buf = ch & 1;
        if (ch + 1 < CHUNKS) loadPref(pr, aI, aJ, whi, wlo, ch + 1);

        const uint32_t bufb = sb + (uint32_t)(BUF0 + buf * BUFSZ);
        const uint32_t aAH = bufb + 0 * TSZ + (uint32_t)(wm) * STR + lrow;
        const uint32_t aAL = bufb + 1 * TSZ + (uint32_t)(wm) * STR + lrow;
        const uint32_t aBH = bufb + 2 * TSZ + (uint32_t)(wn) * STR + lrow;
        const uint32_t aBL = bufb + 3 * TSZ + (uint32_t)(wn) * STR + lrow;

#pragma unroll
        for (int ks = 0; ks < 2; ks++) {
            const uint32_t ko = (uint32_t)(ks * 32);
            uint32_t ah[4][4], al[4][4], bh[2][4], bl[2][4];
#pragma unroll
            for (int i = 0; i < 4; i++) {
                ldm4(ah[i], aAH + (uint32_t)(i * 16) * STR + ko);
                ldm4(al[i], aAL + (uint32_t)(i * 16) * STR + ko);
            }
#pragma unroll
            for (int jp = 0; jp < 2; jp++) {
                ldm4(bh[jp], aBH + (uint32_t)(jp * 16) * STR + ko);
                ldm4(bl[jp], aBL + (uint32_t)(jp * 16) * STR + ko);
            }
            // term 1: hi*hi
#pragma unroll
            for (int i = 0; i < 4; i++)
#pragma unroll
                for (int j = 0; j < 4; j++)
                    mma16816(c[i][j], ah[i], bh[j>>1][j&1], bh[j>>1][(j&1)+2]);
            // term 2: hi*lo
#pragma unroll
            for (int i = 0; i < 4; i++)
#pragma unroll
                for (int j = 0; j < 4; j++)
                    mma16816(c[i][j], ah[i], bl[j>>1][j&1], bl[j>>1][(j&1)+2]);
            // term 3: lo*hi
#pragma unroll
            for (int i = 0; i < 4; i++)
#pragma unroll
                for (int j = 0; j < 4; j++)
                    mma16816(c[i][j], al[i], bh[j>>1][j&1], bh[j>>1][(j&1)+2]);
        }

        if (ch + 1 < CHUNKS) storePref(pr, sm, buf ^ 1, srow, pv, ch + 1, half);
        __syncthreads();
    }

    // epilogue: registers -> gmem, + b2
#pragma unroll
    for (int j = 0; j < 4; j++) {
        const int col = n0 + wn + j * 8 + (lane & 3) * 2;
        const float2 bz = *(const float2*)(b2g + col);
#pragma unroll
        for (int i = 0; i < 4; i++) {
            const int r0 = m0 + wm + i * 16 + (lane >> 2);
            if (r0 < NP) {
                float2 v0 = {c[i][j][0] + bz.x, c[i][j][1] + bz.y};
                *(float2*)(out + ((size_t)(b * NP + r0)) * D + col) = v0;
            }
            const int r1 = r0 + 8;
            if (r1 < NP) {
                float2 v1 = {c[i][j][2] + bz.x, c[i][j][3] + bz.y};
                *(float2*)(out + ((size_t)(b * NP + r1)) * D + col) = v1;
            }
        }
    }
}

extern "C" void kernel_launch(void* const* d_in, const int* in_sizes, int n_in,
                              void* d_out, int out_size)
{
    const float* pf = (const float*)d_in[0];
    const float* W1 = (const float*)d_in[1];
    const float* b1 = (const float*)d_in[2];
    const float* W2 = (const float*)d_in[3];
    const float* b2 = (const float*)d_in[4];
    float* out = (float*)d_out;

    cudaFuncSetAttribute(k2_mma, cudaFuncAttributeMaxDynamicSharedMemorySize, SMEM_K2);

    k0_split<<<(D * D + 255) / 256, 256>>>(W2);

    dim3 g1(16, 8, 1);
    k1_proj<<<g1, 256>>>(pf, W1);

    dim3 g2(8, 4, BATCH);
    k2_mma<<<g2, 256, SMEM_K2>>>(b1, b2, out);
}